// round 12
// baseline (speedup 1.0000x reference)
#include <cuda_runtime.h>
#include <cuda_fp16.h>
#include <cstdint>

#define NN 100000
#define NE 1600000
#define C  128
#define NB 98  // ceil(NN/1024)

// ---------------- device scratch (no allocations allowed) ----------------
// g_deg / g_blk_flag zero on first use (static zero-init); cleanup_k re-zeroes
// at the END of every replay for the next one.
__device__ int      g_deg[NN];
__device__ int      g_off[NN + 1];
__device__ int      g_cursor[NN];
__device__ int      g_blk_agg[NB];
__device__ int      g_blk_pfx[NB];
__device__ volatile int g_blk_flag[NB];
__device__ int      g_csr[NE];
__device__ uint32_t g_x16[(size_t)NN * 64];    // x as half2 words [NN][64]
__device__ uint32_t g_h16[(size_t)NN * 64];    // h as half2 words
__device__ uint32_t g_W1l_h[C * C / 2];        // weights as half2 words [C][64]
__device__ uint32_t g_W1r_h[C * C / 2];
__device__ uint32_t g_W2l_h[C * C / 2];
__device__ uint32_t g_W2r_h[C * C / 2];

__device__ __forceinline__ uint32_t pack_h2(float a, float b) {
    __half2 h = __floats2half2_rn(a, b);
    return *(uint32_t*)&h;
}

// Per-block edge dtype detection (first 64 high words; L2-hot).
__device__ __forceinline__ int detect_is64_block(const void* ei) {
    __shared__ int s_is64;
    if (threadIdx.x < 32) {
        const int* w = (const int*)ei;
        int nz = (w[2 * threadIdx.x + 1] != 0) ? 1 : 0;
        unsigned m = __ballot_sync(0xffffffff, nz);
        if (threadIdx.x == 0) s_is64 = (m == 0);
    }
    __syncthreads();
    return s_is64;
}

__device__ __forceinline__ int4 edge4_at(const void* ei, int base, int is64) {
    if (is64) {
        const longlong2* p = (const longlong2*)((const long long*)ei + base);
        longlong2 u = p[0];
        longlong2 v = p[1];
        return make_int4((int)u.x, (int)u.y, (int)v.x, (int)v.y);
    }
    return *(const int4*)((const int*)ei + base);
}

// ---------------- launch 0: fused cvt (blocks [0,12500)) + hist (rest) -------
#define CVT_BLOCKS 12500                       // NN*32/256
#define HIST_BLOCKS 1563                       // ceil(NE/4/256)

__global__ void __launch_bounds__(256) hist_cvt_k(const void* __restrict__ ei,
                                                  const float4* __restrict__ x4,
                                                  const float* __restrict__ W1l,
                                                  const float* __restrict__ W1r,
                                                  const float* __restrict__ W2l,
                                                  const float* __restrict__ W2r) {
    if (blockIdx.x < CVT_BLOCKS) {
        int i = blockIdx.x * 256 + threadIdx.x;
        float4 v = x4[i];
        ((uint2*)g_x16)[i] = make_uint2(pack_h2(v.x, v.y), pack_h2(v.z, v.w));
        if (i < C * C / 2) {
            g_W1l_h[i] = pack_h2(W1l[2 * i], W1l[2 * i + 1]);
            g_W1r_h[i] = pack_h2(W1r[2 * i], W1r[2 * i + 1]);
            g_W2l_h[i] = pack_h2(W2l[2 * i], W2l[2 * i + 1]);
            g_W2r_h[i] = pack_h2(W2r[2 * i], W2r[2 * i + 1]);
        }
        return;
    }
    int is64 = detect_is64_block(ei);
    int t = (blockIdx.x - CVT_BLOCKS) * 256 + threadIdx.x;   // 4 edges per thread
    if (t < NE / 4) {
        int4 d = edge4_at(ei, NE + t * 4, is64);
        atomicAdd(&g_deg[d.x], 1);
        atomicAdd(&g_deg[d.y], 1);
        atomicAdd(&g_deg[d.z], 1);
        atomicAdd(&g_deg[d.w], 1);
    }
}

// ---------------- launch 1: single-pass decoupled-lookback scan ----------------
__global__ void __launch_bounds__(1024) scan_k() {
    __shared__ int s[1024];
    __shared__ int blk_base;
    int b = blockIdx.x;
    int i = b * 1024 + threadIdx.x;
    int v = (i < NN) ? g_deg[i] : 0;
    s[threadIdx.x] = v;
    __syncthreads();
    for (int d = 1; d < 1024; d <<= 1) {
        int t = (threadIdx.x >= d) ? s[threadIdx.x - d] : 0;
        __syncthreads();
        s[threadIdx.x] += t;
        __syncthreads();
    }
    if (threadIdx.x == 1023) {
        int total = s[1023];
        g_blk_agg[b] = total;
        __threadfence();
        g_blk_flag[b] = 1;
        int base = 0;
        for (int p = b - 1; p >= 0; p--) {
            int f;
            while ((f = g_blk_flag[p]) == 0) {}
            if (f == 2) { base += g_blk_pfx[p]; break; }
            base += g_blk_agg[p];
        }
        g_blk_pfx[b] = base + total;
        __threadfence();
        g_blk_flag[b] = 2;
        blk_base = base;
    }
    __syncthreads();
    if (i < NN) {
        int o = blk_base + s[threadIdx.x] - v;
        g_off[i] = o;
        g_cursor[i] = o;
    }
    if (i == 0) g_off[NN] = NE;
}

// ---------------- launch 2: CSR fill, 4 edges/thread ----------------
__global__ void __launch_bounds__(256) csr_fill_k(const void* __restrict__ ei) {
    int is64 = detect_is64_block(ei);
    int t = blockIdx.x * 256 + threadIdx.x;
    if (t < NE / 4) {
        int4 s = edge4_at(ei, t * 4, is64);
        int4 d = edge4_at(ei, NE + t * 4, is64);
        g_csr[atomicAdd(&g_cursor[d.x], 1)] = s.x;
        g_csr[atomicAdd(&g_cursor[d.y], 1)] = s.y;
        g_csr[atomicAdd(&g_cursor[d.z], 1)] = s.z;
        g_csr[atomicAdd(&g_cursor[d.w], 1)] = s.w;
    }
}

// ---------------- fused aggregate + dual GEMM (fp16, m16n8k16, fp32 accum) ----
// Phase 1: warp w aggregates nodes [w*16, w*16+16) of this block's 128-node
//          slab into the smem A-tile Am (mean, fp16, fragment-friendly layout).
// Phase 2: out[i][c] = (relu)( mean[i]·Wl[c] + feat[i]·Wr[c] + bias[c] )
//          chunks 0..3 read A from Am (persistent), 4..7 stream feat via
//          cp.async ping-pong; W always streams. W chunk 0 prefetch overlaps
//          the aggregation phase.

#define ROWW  20                      // words per streaming smem row (16 + 4 pad)
#define BUFW  (128 * ROWW)
#define MROWW 68                      // words per Am row (64 + 4 pad)
#define FUSED_SMEM_BYTES ((128 * MROWW + 4 * BUFW) * 4)   // 75776 B

__device__ __forceinline__ void cp_async16(uint32_t smem, const void* gptr, int src_sz) {
    asm volatile("cp.async.ca.shared.global [%0], [%1], 16, %2;"
                 :: "r"(smem), "l"(gptr), "r"(src_sz));
}
__device__ __forceinline__ void cp_commit() {
    asm volatile("cp.async.commit_group;");
}
template <int N>
__device__ __forceinline__ void cp_wait() {
    asm volatile("cp.async.wait_group %0;" :: "n"(N));
}

__device__ __forceinline__ void acc_h(float4& a, uint2 u) {
    float2 f0 = __half22float2(*(__half2*)&u.x);
    float2 f1 = __half22float2(*(__half2*)&u.y);
    a.x += f0.x; a.y += f0.y; a.z += f1.x; a.w += f1.y;
}

template <bool RELU>   // RELU layer emits fp16 h only; final layer emits fp32
__global__ void __launch_bounds__(256, 2) agg_gemm_k(
    const uint32_t* __restrict__ feat, // x16 (layer1) / h16 (layer2): gather src AND A2
    const uint32_t* __restrict__ Wl,   // [C][64] fp16
    const uint32_t* __restrict__ Wr,   // [C][64] fp16
    const float*    __restrict__ bias, // [C]
    float*          __restrict__ outp, // [NN][C] fp32 (final layer)
    uint32_t*       __restrict__ out16)// [NN][64] fp16 (hidden layer)
{
    extern __shared__ uint32_t smem[];
    uint32_t* Am = smem;                    // [128][MROWW] mean tile
    uint32_t* As = smem + 128 * MROWW;      // [2][BUFW] feat stream
    uint32_t* Ws = As + 2 * BUFW;           // [2][BUFW] weight stream

    const int tid  = threadIdx.x;
    const int lane = tid & 31;
    const int wid  = tid >> 5;
    const int nodeBase = blockIdx.x * 128;

    const uint32_t as_base = (uint32_t)__cvta_generic_to_shared(As);
    const uint32_t ws_base = (uint32_t)__cvta_generic_to_shared(Ws);

    auto stage = [&](int s, int buf) {
        const uint32_t* W = (s < 4) ? Wl : Wr;
        const int kw = (s & 3) * 16;
        #pragma unroll
        for (int t = 0; t < 2; t++) {
            int idx = tid + t * 256;
            int row = idx >> 2;
            int q   = idx & 3;
            cp_async16(ws_base + (buf * BUFW + row * ROWW + q * 4) * 4,
                       &W[row * 64 + kw + q * 4], 16);
        }
        if (s >= 4) {
            #pragma unroll
            for (int t = 0; t < 2; t++) {
                int idx = tid + t * 256;
                int row = idx >> 2;
                int q   = idx & 3;
                int gnode = nodeBase + row;
                cp_async16(as_base + (buf * BUFW + row * ROWW + q * 4) * 4,
                           &feat[(size_t)gnode * 64 + kw + q * 4],
                           (gnode < NN) ? 16 : 0);
            }
        }
        cp_commit();
    };

    stage(0, 0);   // W chunk 0 streams while we aggregate

    // ---- Phase 1: aggregation into Am (warp w -> 16 nodes) ----
    const uint2* xv = (const uint2*)feat;
    #pragma unroll 1
    for (int i = 0; i < 16; i++) {
        int r = wid * 16 + i;
        int node = nodeBase + r;
        if (node >= NN) break;
        int start = g_off[node];
        int end   = g_off[node + 1];
        float4 acc = make_float4(0.f, 0.f, 0.f, 0.f);
        int k = start;
        for (; k + 16 <= end; k += 16) {          // deep MLP: 16 gathers in flight
            int idx[16];
            #pragma unroll
            for (int j = 0; j < 16; j++) idx[j] = g_csr[k + j];
            uint2 v[16];
            #pragma unroll
            for (int j = 0; j < 16; j++) v[j] = xv[(size_t)idx[j] * 32 + lane];
            #pragma unroll
            for (int j = 0; j < 16; j++) acc_h(acc, v[j]);
        }
        for (; k + 4 <= end; k += 4) {
            int idx[4];
            #pragma unroll
            for (int j = 0; j < 4; j++) idx[j] = g_csr[k + j];
            uint2 v[4];
            #pragma unroll
            for (int j = 0; j < 4; j++) v[j] = xv[(size_t)idx[j] * 32 + lane];
            #pragma unroll
            for (int j = 0; j < 4; j++) acc_h(acc, v[j]);
        }
        for (; k < end; k++) acc_h(acc, xv[(size_t)g_csr[k] * 32 + lane]);
        int deg = end - start;
        float inv = 1.0f / (float)(deg > 0 ? deg : 1);
        acc.x *= inv; acc.y *= inv; acc.z *= inv; acc.w *= inv;
        *(uint2*)&Am[r * MROWW + 2 * lane] =
            make_uint2(pack_h2(acc.x, acc.y), pack_h2(acc.z, acc.w));
    }

    // ---- Phase 2: GEMM ----
    const int warpRow = wid >> 2;
    const int warpCol = wid & 3;
    const int lr = lane >> 2;
    const int lc = lane & 3;

    float acc[4][4][4] = {};

    // chunks 0..3: A from Am (no wait needed for A), W = Wl streamed
    #pragma unroll 1
    for (int s = 0; s < 4; s++) {
        const int buf = s & 1;
        stage(s + 1, buf ^ 1);
        cp_wait<1>();
        __syncthreads();          // W chunk s ready; also orders Am on s==0

        const uint32_t* Wb = Ws + buf * BUFW;
        const int abase = s * 16;
        #pragma unroll
        for (int ks = 0; ks < 2; ks++) {
            const int k0 = ks * 8;
            uint32_t bf[4][2];
            #pragma unroll
            for (int nt = 0; nt < 4; nt++) {
                int c = warpCol * 32 + nt * 8 + lr;
                bf[nt][0] = Wb[c * ROWW + k0 + lc];
                bf[nt][1] = Wb[c * ROWW + k0 + lc + 4];
            }
            #pragma unroll
            for (int mt = 0; mt < 4; mt++) {
                int r = warpRow * 64 + mt * 16 + lr;
                uint32_t a0 = Am[r * MROWW + abase + k0 + lc];
                uint32_t a1 = Am[(r + 8) * MROWW + abase + k0 + lc];
                uint32_t a2 = Am[r * MROWW + abase + k0 + lc + 4];
                uint32_t a3 = Am[(r + 8) * MROWW + abase + k0 + lc + 4];
                #pragma unroll
                for (int nt = 0; nt < 4; nt++) {
                    asm volatile(
                        "mma.sync.aligned.m16n8k16.row.col.f32.f16.f16.f32 "
                        "{%0,%1,%2,%3}, {%4,%5,%6,%7}, {%8,%9}, {%0,%1,%2,%3};"
                        : "+f"(acc[mt][nt][0]), "+f"(acc[mt][nt][1]),
                          "+f"(acc[mt][nt][2]), "+f"(acc[mt][nt][3])
                        : "r"(a0), "r"(a1), "r"(a2), "r"(a3),
                          "r"(bf[nt][0]), "r"(bf[nt][1]));
                }
            }
        }
        __syncthreads();
    }

    // chunks 4..7: A = feat streamed, W = Wr streamed
    #pragma unroll 1
    for (int s = 4; s < 8; s++) {
        const int buf = s & 1;
        if (s < 7) stage(s + 1, buf ^ 1);
        if (s < 7) cp_wait<1>(); else cp_wait<0>();
        __syncthreads();

        const uint32_t* Ab = As + buf * BUFW;
        const uint32_t* Wb = Ws + buf * BUFW;
        #pragma unroll
        for (int ks = 0; ks < 2; ks++) {
            const int k0 = ks * 8;
            uint32_t bf[4][2];
            #pragma unroll
            for (int nt = 0; nt < 4; nt++) {
                int c = warpCol * 32 + nt * 8 + lr;
                bf[nt][0] = Wb[c * ROWW + k0 + lc];
                bf[nt][1] = Wb[c * ROWW + k0 + lc + 4];
            }
            #pragma unroll
            for (int mt = 0; mt < 4; mt++) {
                int r = warpRow * 64 + mt * 16 + lr;
                uint32_t a0 = Ab[r * ROWW + k0 + lc];
                uint32_t a1 = Ab[(r + 8) * ROWW + k0 + lc];
                uint32_t a2 = Ab[r * ROWW + k0 + lc + 4];
                uint32_t a3 = Ab[(r + 8) * ROWW + k0 + lc + 4];
                #pragma unroll
                for (int nt = 0; nt < 4; nt++) {
                    asm volatile(
                        "mma.sync.aligned.m16n8k16.row.col.f32.f16.f16.f32 "
                        "{%0,%1,%2,%3}, {%4,%5,%6,%7}, {%8,%9}, {%0,%1,%2,%3};"
                        : "+f"(acc[mt][nt][0]), "+f"(acc[mt][nt][1]),
                          "+f"(acc[mt][nt][2]), "+f"(acc[mt][nt][3])
                        : "r"(a0), "r"(a1), "r"(a2), "r"(a3),
                          "r"(bf[nt][0]), "r"(bf[nt][1]));
                }
            }
        }
        __syncthreads();
    }

    // ---- epilogue ----
    #pragma unroll
    for (int nt = 0; nt < 4; nt++) {
        int c = warpCol * 32 + nt * 8 + 2 * lc;
        float bb0 = bias[c];
        float bb1 = bias[c + 1];
        #pragma unroll
        for (int mt = 0; mt < 4; mt++) {
            int r0 = nodeBase + warpRow * 64 + mt * 16 + lr;
            int r1 = r0 + 8;
            float o0 = acc[mt][nt][0] + bb0;
            float o1 = acc[mt][nt][1] + bb1;
            float o2 = acc[mt][nt][2] + bb0;
            float o3 = acc[mt][nt][3] + bb1;
            if (RELU) {
                o0 = fmaxf(o0, 0.f); o1 = fmaxf(o1, 0.f);
                o2 = fmaxf(o2, 0.f); o3 = fmaxf(o3, 0.f);
                if (r0 < NN) out16[(size_t)r0 * 64 + (c >> 1)] = pack_h2(o0, o1);
                if (r1 < NN) out16[(size_t)r1 * 64 + (c >> 1)] = pack_h2(o2, o3);
            } else {
                if (r0 < NN) *(float2*)&outp[(size_t)r0 * C + c] = make_float2(o0, o1);
                if (r1 < NN) *(float2*)&outp[(size_t)r1 * C + c] = make_float2(o2, o3);
            }
        }
    }
}

// ---------------- trailing cleanup for next replay ----------------
__global__ void __launch_bounds__(256) cleanup_k() {
    int i = blockIdx.x * blockDim.x + threadIdx.x;
    if (i < NN) g_deg[i] = 0;
    if (i < NB) g_blk_flag[i] = 0;
}

// ---------------- launch ----------------
extern "C" void kernel_launch(void* const* d_in, const int* in_sizes, int n_in,
                              void* d_out, int out_size) {
    const float* x   = (const float*)d_in[0];
    const void*  ei  = d_in[1];
    const float* W1l = (const float*)d_in[2];
    const float* b1  = (const float*)d_in[3];
    const float* W1r = (const float*)d_in[4];
    const float* W2l = (const float*)d_in[5];
    const float* b2  = (const float*)d_in[6];
    const float* W2r = (const float*)d_in[7];
    float* out = (float*)d_out;

    uint32_t *x16, *h16, *w1l, *w1r, *w2l, *w2r;
    cudaGetSymbolAddress((void**)&x16, g_x16);
    cudaGetSymbolAddress((void**)&h16, g_h16);
    cudaGetSymbolAddress((void**)&w1l, g_W1l_h);
    cudaGetSymbolAddress((void**)&w1r, g_W1r_h);
    cudaGetSymbolAddress((void**)&w2l, g_W2l_h);
    cudaGetSymbolAddress((void**)&w2r, g_W2r_h);

    cudaFuncSetAttribute(agg_gemm_k<true>,
                         cudaFuncAttributeMaxDynamicSharedMemorySize, FUSED_SMEM_BYTES);
    cudaFuncSetAttribute(agg_gemm_k<false>,
                         cudaFuncAttributeMaxDynamicSharedMemorySize, FUSED_SMEM_BYTES);

    hist_cvt_k<<<CVT_BLOCKS + HIST_BLOCKS, 256>>>(ei, (const float4*)x,
                                                  W1l, W1r, W2l, W2r);           // 0
    scan_k<<<NB, 1024>>>();                                                      // 1
    csr_fill_k<<<(NE / 4 + 255) / 256, 256>>>(ei);                               // 2

    const int fusedGrid = (NN + 127) / 128;  // 782

    agg_gemm_k<true><<<fusedGrid, 256, FUSED_SMEM_BYTES>>>(
        x16, w1l, w1r, b1, nullptr, h16);                                        // 3 <- profiled
    agg_gemm_k<false><<<fusedGrid, 256, FUSED_SMEM_BYTES>>>(
        h16, w2l, w2r, b2, out, nullptr);                                        // 4
    cleanup_k<<<(NN + 255) / 256, 256>>>();                                      // 5
}

// round 13
// speedup vs baseline: 1.3493x; 1.3493x over previous
#include <cuda_runtime.h>
#include <cuda_fp16.h>
#include <cstdint>

#define NN 100000
#define NE 1600000
#define C  128
#define NB 98  // ceil(NN/1024)

// ---------------- device scratch (no allocations allowed) ----------------
// g_deg / g_blk_flag zero on first use (static zero-init); cleanup_k re-zeroes
// at the END of every replay for the next one.
__device__ int      g_deg[NN];
__device__ int      g_off[NN + 1];
__device__ int      g_cursor[NN];
__device__ int      g_blk_agg[NB];
__device__ int      g_blk_pfx[NB];
__device__ volatile int g_blk_flag[NB];
__device__ int      g_csr[NE];
__device__ uint32_t g_x16[(size_t)NN * 64];    // x     as half2 words [NN][64]
__device__ uint32_t g_mean16[(size_t)NN * 64]; // mean  as half2 words
__device__ uint32_t g_h16[(size_t)NN * 64];    // h     as half2 words
__device__ uint32_t g_W1l_h[C * C / 2];        // weights as half2 words [C][64]
__device__ uint32_t g_W1r_h[C * C / 2];
__device__ uint32_t g_W2l_h[C * C / 2];
__device__ uint32_t g_W2r_h[C * C / 2];

__device__ __forceinline__ uint32_t pack_h2(float a, float b) {
    __half2 h = __floats2half2_rn(a, b);
    return *(uint32_t*)&h;
}

// Per-block edge dtype detection (first 64 high words; L2-hot).
__device__ __forceinline__ int detect_is64_block(const void* ei) {
    __shared__ int s_is64;
    if (threadIdx.x < 32) {
        const int* w = (const int*)ei;
        int nz = (w[2 * threadIdx.x + 1] != 0) ? 1 : 0;
        unsigned m = __ballot_sync(0xffffffff, nz);
        if (threadIdx.x == 0) s_is64 = (m == 0);
    }
    __syncthreads();
    return s_is64;
}

__device__ __forceinline__ int4 edge4_at(const void* ei, int base, int is64) {
    if (is64) {
        const longlong2* p = (const longlong2*)((const long long*)ei + base);
        longlong2 u = p[0];
        longlong2 v = p[1];
        return make_int4((int)u.x, (int)u.y, (int)v.x, (int)v.y);
    }
    return *(const int4*)((const int*)ei + base);
}

// ---------------- launch 0: fused cvt (blocks [0,12500)) + hist (rest) -------
#define CVT_BLOCKS 12500                       // NN*32/256
#define HIST_BLOCKS 1563                       // ceil(NE/4/256)

__global__ void __launch_bounds__(256) hist_cvt_k(const void* __restrict__ ei,
                                                  const float4* __restrict__ x4,
                                                  const float* __restrict__ W1l,
                                                  const float* __restrict__ W1r,
                                                  const float* __restrict__ W2l,
                                                  const float* __restrict__ W2r) {
    if (blockIdx.x < CVT_BLOCKS) {
        int i = blockIdx.x * 256 + threadIdx.x;
        float4 v = x4[i];
        ((uint2*)g_x16)[i] = make_uint2(pack_h2(v.x, v.y), pack_h2(v.z, v.w));
        if (i < C * C / 2) {
            g_W1l_h[i] = pack_h2(W1l[2 * i], W1l[2 * i + 1]);
            g_W1r_h[i] = pack_h2(W1r[2 * i], W1r[2 * i + 1]);
            g_W2l_h[i] = pack_h2(W2l[2 * i], W2l[2 * i + 1]);
            g_W2r_h[i] = pack_h2(W2r[2 * i], W2r[2 * i + 1]);
        }
        return;
    }
    int is64 = detect_is64_block(ei);
    int t = (blockIdx.x - CVT_BLOCKS) * 256 + threadIdx.x;   // 4 edges per thread
    if (t < NE / 4) {
        int4 d = edge4_at(ei, NE + t * 4, is64);
        atomicAdd(&g_deg[d.x], 1);
        atomicAdd(&g_deg[d.y], 1);
        atomicAdd(&g_deg[d.z], 1);
        atomicAdd(&g_deg[d.w], 1);
    }
}

// ---------------- launch 1: single-pass decoupled-lookback scan ----------------
__global__ void __launch_bounds__(1024) scan_k() {
    __shared__ int s[1024];
    __shared__ int blk_base;
    int b = blockIdx.x;
    int i = b * 1024 + threadIdx.x;
    int v = (i < NN) ? g_deg[i] : 0;
    s[threadIdx.x] = v;
    __syncthreads();
    for (int d = 1; d < 1024; d <<= 1) {
        int t = (threadIdx.x >= d) ? s[threadIdx.x - d] : 0;
        __syncthreads();
        s[threadIdx.x] += t;
        __syncthreads();
    }
    if (threadIdx.x == 1023) {
        int total = s[1023];
        g_blk_agg[b] = total;
        __threadfence();
        g_blk_flag[b] = 1;
        int base = 0;
        for (int p = b - 1; p >= 0; p--) {
            int f;
            while ((f = g_blk_flag[p]) == 0) {}
            if (f == 2) { base += g_blk_pfx[p]; break; }
            base += g_blk_agg[p];
        }
        g_blk_pfx[b] = base + total;
        __threadfence();
        g_blk_flag[b] = 2;
        blk_base = base;
    }
    __syncthreads();
    if (i < NN) {
        int o = blk_base + s[threadIdx.x] - v;
        g_off[i] = o;
        g_cursor[i] = o;
    }
    if (i == 0) g_off[NN] = NE;
}

// ---------------- launch 2: CSR fill, 4 edges/thread ----------------
__global__ void __launch_bounds__(256) csr_fill_k(const void* __restrict__ ei) {
    int is64 = detect_is64_block(ei);
    int t = blockIdx.x * 256 + threadIdx.x;
    if (t < NE / 4) {
        int4 s = edge4_at(ei, t * 4, is64);
        int4 d = edge4_at(ei, NE + t * 4, is64);
        g_csr[atomicAdd(&g_cursor[d.x], 1)] = s.x;
        g_csr[atomicAdd(&g_cursor[d.y], 1)] = s.y;
        g_csr[atomicAdd(&g_cursor[d.z], 1)] = s.z;
        g_csr[atomicAdd(&g_cursor[d.w], 1)] = s.w;
    }
}

// ---------------- launch 3 (PROFILED): fp16 mean aggregation, 1 warp/node ----
// Pairwise HADD2 pre-accumulation halves cvt+fadd issue count; vector int4
// index loads quarter the index-load issue count.
__device__ __forceinline__ void acc_h(float4& a, uint2 u) {
    float2 f0 = __half22float2(*(__half2*)&u.x);
    float2 f1 = __half22float2(*(__half2*)&u.y);
    a.x += f0.x; a.y += f0.y; a.z += f1.x; a.w += f1.y;
}

__device__ __forceinline__ void acc_pair(float4& a, uint2 u, uint2 w) {
    __half2 s0 = __hadd2(*(__half2*)&u.x, *(__half2*)&w.x);
    __half2 s1 = __hadd2(*(__half2*)&u.y, *(__half2*)&w.y);
    float2 f0 = __half22float2(s0);
    float2 f1 = __half22float2(s1);
    a.x += f0.x; a.y += f0.y; a.z += f1.x; a.w += f1.y;
}

__global__ void __launch_bounds__(256) aggregate_k(const uint32_t* __restrict__ xin,
                                                   uint32_t* __restrict__ outp) {
    int warp = (blockIdx.x * blockDim.x + threadIdx.x) >> 5;
    int lane = threadIdx.x & 31;
    if (warp >= NN) return;
    int start = g_off[warp];
    int end   = g_off[warp + 1];
    const uint2* xv = (const uint2*)xin;
    float4 acc = make_float4(0.f, 0.f, 0.f, 0.f);
    int k = start;
    // peel to 16B alignment of g_csr
    for (; k < end && (k & 3); k++) acc_h(acc, xv[(size_t)g_csr[k] * 32 + lane]);
    // main: 8 edges per iter, int4 index loads, pairwise half accumulation
    for (; k + 8 <= end; k += 8) {
        int4 ia = *(const int4*)&g_csr[k];
        int4 ib = *(const int4*)&g_csr[k + 4];
        uint2 v0 = xv[(size_t)ia.x * 32 + lane];
        uint2 v1 = xv[(size_t)ia.y * 32 + lane];
        uint2 v2 = xv[(size_t)ia.z * 32 + lane];
        uint2 v3 = xv[(size_t)ia.w * 32 + lane];
        uint2 v4 = xv[(size_t)ib.x * 32 + lane];
        uint2 v5 = xv[(size_t)ib.y * 32 + lane];
        uint2 v6 = xv[(size_t)ib.z * 32 + lane];
        uint2 v7 = xv[(size_t)ib.w * 32 + lane];
        acc_pair(acc, v0, v1);
        acc_pair(acc, v2, v3);
        acc_pair(acc, v4, v5);
        acc_pair(acc, v6, v7);
    }
    // 4-edge remainder
    if (k + 4 <= end) {
        int4 ia = *(const int4*)&g_csr[k];
        uint2 v0 = xv[(size_t)ia.x * 32 + lane];
        uint2 v1 = xv[(size_t)ia.y * 32 + lane];
        uint2 v2 = xv[(size_t)ia.z * 32 + lane];
        uint2 v3 = xv[(size_t)ia.w * 32 + lane];
        acc_pair(acc, v0, v1);
        acc_pair(acc, v2, v3);
        k += 4;
    }
    // scalar tail
    for (; k < end; k++) acc_h(acc, xv[(size_t)g_csr[k] * 32 + lane]);

    int deg = end - start;
    float inv = 1.0f / (float)(deg > 0 ? deg : 1);
    acc.x *= inv; acc.y *= inv; acc.z *= inv; acc.w *= inv;
    ((uint2*)outp)[(size_t)warp * 32 + lane] =
        make_uint2(pack_h2(acc.x, acc.y), pack_h2(acc.z, acc.w));
}

// ---------------- fp16 tensor-core fused dual GEMM (m16n8k16, fp32 accum) ----
#define ROWW 20                       // words per smem row (16 data + 4 pad)
#define BUFW (128 * ROWW)             // words per buffer

__device__ __forceinline__ void cp_async16(uint32_t smem, const void* gptr, int src_sz) {
    asm volatile("cp.async.ca.shared.global [%0], [%1], 16, %2;"
                 :: "r"(smem), "l"(gptr), "r"(src_sz));
}
__device__ __forceinline__ void cp_commit() {
    asm volatile("cp.async.commit_group;");
}
template <int N>
__device__ __forceinline__ void cp_wait() {
    asm volatile("cp.async.wait_group %0;" :: "n"(N));
}

template <bool RELU>   // RELU version emits fp16 output only
__global__ void __launch_bounds__(256) gemm_f16_k(
    const uint32_t* __restrict__ A1,   // mean16 [NN][64]
    const uint32_t* __restrict__ A2,   // x16/h16 [NN][64]
    const uint32_t* __restrict__ Wl,   // [C][64] fp16
    const uint32_t* __restrict__ Wr,   // [C][64] fp16
    const float*    __restrict__ bias, // [C]
    float*          __restrict__ outp, // [NN][C] fp32 (final layer)
    uint32_t*       __restrict__ out16)// [NN][64] fp16 (hidden layer)
{
    __shared__ uint32_t As[2][BUFW];
    __shared__ uint32_t Ws[2][BUFW];

    const int tid  = threadIdx.x;
    const int lane = tid & 31;
    const int wid  = tid >> 5;
    const int warpRow = wid >> 2;
    const int warpCol = wid & 3;
    const int nodeBase = blockIdx.x * 128;

    const int lr = lane >> 2;
    const int lc = lane & 3;

    const uint32_t as_base = (uint32_t)__cvta_generic_to_shared(&As[0][0]);
    const uint32_t ws_base = (uint32_t)__cvta_generic_to_shared(&Ws[0][0]);

    float acc[4][4][4] = {};

    auto stage = [&](int s, int buf) {
        const int half = s >> 2;
        const int kw   = (s & 3) * 16;
        const uint32_t* A = half ? A2 : A1;
        const uint32_t* W = half ? Wr : Wl;
        #pragma unroll
        for (int t = 0; t < 2; t++) {
            int idx = tid + t * 256;
            int row = idx >> 2;
            int q   = idx & 3;
            int gnode = nodeBase + row;
            uint32_t off = (buf * BUFW + row * ROWW + q * 4) * 4;
            cp_async16(as_base + off, &A[(size_t)gnode * 64 + kw + q * 4],
                       (gnode < NN) ? 16 : 0);
            cp_async16(ws_base + off, &W[row * 64 + kw + q * 4], 16);
        }
        cp_commit();
    };

    stage(0, 0);

    #pragma unroll 1
    for (int s = 0; s < 8; s++) {
        const int buf = s & 1;
        if (s < 7) stage(s + 1, buf ^ 1);
        if (s < 7) cp_wait<1>(); else cp_wait<0>();
        __syncthreads();

        const uint32_t* Ab = &As[buf][0];
        const uint32_t* Wb = &Ws[buf][0];

        #pragma unroll
        for (int ks = 0; ks < 2; ks++) {
            const int k0 = ks * 8;
            uint32_t bf[4][2];
            #pragma unroll
            for (int nt = 0; nt < 4; nt++) {
                int c = warpCol * 32 + nt * 8 + lr;
                bf[nt][0] = Wb[c * ROWW + k0 + lc];
                bf[nt][1] = Wb[c * ROWW + k0 + lc + 4];
            }
            #pragma unroll
            for (int mt = 0; mt < 4; mt++) {
                int r = warpRow * 64 + mt * 16 + lr;
                uint32_t a0 = Ab[r * ROWW + k0 + lc];
                uint32_t a1 = Ab[(r + 8) * ROWW + k0 + lc];
                uint32_t a2 = Ab[r * ROWW + k0 + lc + 4];
                uint32_t a3 = Ab[(r + 8) * ROWW + k0 + lc + 4];
                #pragma unroll
                for (int nt = 0; nt < 4; nt++) {
                    asm volatile(
                        "mma.sync.aligned.m16n8k16.row.col.f32.f16.f16.f32 "
                        "{%0,%1,%2,%3}, {%4,%5,%6,%7}, {%8,%9}, {%0,%1,%2,%3};"
                        : "+f"(acc[mt][nt][0]), "+f"(acc[mt][nt][1]),
                          "+f"(acc[mt][nt][2]), "+f"(acc[mt][nt][3])
                        : "r"(a0), "r"(a1), "r"(a2), "r"(a3),
                          "r"(bf[nt][0]), "r"(bf[nt][1]));
                }
            }
        }
        __syncthreads();
    }

    #pragma unroll
    for (int nt = 0; nt < 4; nt++) {
        int c = warpCol * 32 + nt * 8 + 2 * lc;
        float bb0 = bias[c];
        float bb1 = bias[c + 1];
        #pragma unroll
        for (int mt = 0; mt < 4; mt++) {
            int r0 = nodeBase + warpRow * 64 + mt * 16 + lr;
            int r1 = r0 + 8;
            float o0 = acc[mt][nt][0] + bb0;
            float o1 = acc[mt][nt][1] + bb1;
            float o2 = acc[mt][nt][2] + bb0;
            float o3 = acc[mt][nt][3] + bb1;
            if (RELU) {
                o0 = fmaxf(o0, 0.f); o1 = fmaxf(o1, 0.f);
                o2 = fmaxf(o2, 0.f); o3 = fmaxf(o3, 0.f);
                if (r0 < NN) out16[(size_t)r0 * 64 + (c >> 1)] = pack_h2(o0, o1);
                if (r1 < NN) out16[(size_t)r1 * 64 + (c >> 1)] = pack_h2(o2, o3);
            } else {
                if (r0 < NN) *(float2*)&outp[(size_t)r0 * C + c] = make_float2(o0, o1);
                if (r1 < NN) *(float2*)&outp[(size_t)r1 * C + c] = make_float2(o2, o3);
            }
        }
    }
}

// ---------------- trailing cleanup for next replay ----------------
__global__ void __launch_bounds__(256) cleanup_k() {
    int i = blockIdx.x * blockDim.x + threadIdx.x;
    if (i < NN) g_deg[i] = 0;
    if (i < NB) g_blk_flag[i] = 0;
}

// ---------------- launch ----------------
extern "C" void kernel_launch(void* const* d_in, const int* in_sizes, int n_in,
                              void* d_out, int out_size) {
    const float* x   = (const float*)d_in[0];
    const void*  ei  = d_in[1];
    const float* W1l = (const float*)d_in[2];
    const float* b1  = (const float*)d_in[3];
    const float* W1r = (const float*)d_in[4];
    const float* W2l = (const float*)d_in[5];
    const float* b2  = (const float*)d_in[6];
    const float* W2r = (const float*)d_in[7];
    float* out = (float*)d_out;

    uint32_t *x16, *mean16, *h16, *w1l, *w1r, *w2l, *w2r;
    cudaGetSymbolAddress((void**)&x16,    g_x16);
    cudaGetSymbolAddress((void**)&mean16, g_mean16);
    cudaGetSymbolAddress((void**)&h16,    g_h16);
    cudaGetSymbolAddress((void**)&w1l,    g_W1l_h);
    cudaGetSymbolAddress((void**)&w1r,    g_W1r_h);
    cudaGetSymbolAddress((void**)&w2l,    g_W2l_h);
    cudaGetSymbolAddress((void**)&w2r,    g_W2r_h);

    hist_cvt_k<<<CVT_BLOCKS + HIST_BLOCKS, 256>>>(ei, (const float4*)x,
                                                  W1l, W1r, W2l, W2r);           // 0
    scan_k<<<NB, 1024>>>();                                                      // 1
    csr_fill_k<<<(NE / 4 + 255) / 256, 256>>>(ei);                               // 2

    const int gemmGrid = (NN + 127) / 128;  // 782

    aggregate_k<<<(NN * 32 + 255) / 256, 256>>>(x16, mean16);                    // 3 <- profiled
    gemm_f16_k<true><<<gemmGrid, 256>>>(mean16, x16, w1l, w1r, b1, nullptr, h16); // 4
    aggregate_k<<<(NN * 32 + 255) / 256, 256>>>(h16, mean16);                    // 5
    gemm_f16_k<false><<<gemmGrid, 256>>>(mean16, h16, w2l, w2r, b2, out, nullptr); // 6
    cleanup_k<<<(NN + 255) / 256, 256>>>();                                      // 7
}

// round 14
// speedup vs baseline: 1.3896x; 1.0299x over previous
#include <cuda_runtime.h>
#include <cuda_fp16.h>
#include <cstdint>

#define NN 100000
#define NE 1600000
#define C  128
#define NB 98  // ceil(NN/1024)

// ---------------- device scratch (no allocations allowed) ----------------
// g_deg / g_blk_flag zero on first use (static zero-init); cleanup_k re-zeroes
// at the END of every replay for the next one.
__device__ int      g_deg[NN];
__device__ int      g_off[NN + 1];
__device__ int      g_cursor[NN];
__device__ int      g_blk_agg[NB];
__device__ int      g_blk_pfx[NB];
__device__ volatile int g_blk_flag[NB];
__device__ int      g_csr[NE];
__device__ uint32_t g_x16[(size_t)NN * 64];    // x     as half2 words [NN][64]
__device__ uint32_t g_mean16[(size_t)NN * 64]; // mean  as half2 words
__device__ uint32_t g_h16[(size_t)NN * 64];    // h     as half2 words
__device__ uint32_t g_W1l_h[C * C / 2];        // weights as half2 words [C][64]
__device__ uint32_t g_W1r_h[C * C / 2];
__device__ uint32_t g_W2l_h[C * C / 2];
__device__ uint32_t g_W2r_h[C * C / 2];

__device__ __forceinline__ uint32_t pack_h2(float a, float b) {
    __half2 h = __floats2half2_rn(a, b);
    return *(uint32_t*)&h;
}

// Per-block edge dtype detection (first 64 high words; L2-hot).
__device__ __forceinline__ int detect_is64_block(const void* ei) {
    __shared__ int s_is64;
    if (threadIdx.x < 32) {
        const int* w = (const int*)ei;
        int nz = (w[2 * threadIdx.x + 1] != 0) ? 1 : 0;
        unsigned m = __ballot_sync(0xffffffff, nz);
        if (threadIdx.x == 0) s_is64 = (m == 0);
    }
    __syncthreads();
    return s_is64;
}

__device__ __forceinline__ int4 edge4_at(const void* ei, int base, int is64) {
    if (is64) {
        const longlong2* p = (const longlong2*)((const long long*)ei + base);
        longlong2 u = p[0];
        longlong2 v = p[1];
        return make_int4((int)u.x, (int)u.y, (int)v.x, (int)v.y);
    }
    return *(const int4*)((const int*)ei + base);
}

// ---------------- launch 0: fused cvt (blocks [0,12500)) + hist (rest) -------
#define CVT_BLOCKS 12500                       // NN*32/256
#define HIST_BLOCKS 1563                       // ceil(NE/4/256)

__global__ void __launch_bounds__(256) hist_cvt_k(const void* __restrict__ ei,
                                                  const float4* __restrict__ x4,
                                                  const float* __restrict__ W1l,
                                                  const float* __restrict__ W1r,
                                                  const float* __restrict__ W2l,
                                                  const float* __restrict__ W2r) {
    if (blockIdx.x < CVT_BLOCKS) {
        int i = blockIdx.x * 256 + threadIdx.x;
        float4 v = x4[i];
        ((uint2*)g_x16)[i] = make_uint2(pack_h2(v.x, v.y), pack_h2(v.z, v.w));
        if (i < C * C / 2) {
            g_W1l_h[i] = pack_h2(W1l[2 * i], W1l[2 * i + 1]);
            g_W1r_h[i] = pack_h2(W1r[2 * i], W1r[2 * i + 1]);
            g_W2l_h[i] = pack_h2(W2l[2 * i], W2l[2 * i + 1]);
            g_W2r_h[i] = pack_h2(W2r[2 * i], W2r[2 * i + 1]);
        }
        return;
    }
    int is64 = detect_is64_block(ei);
    int t = (blockIdx.x - CVT_BLOCKS) * 256 + threadIdx.x;   // 4 edges per thread
    if (t < NE / 4) {
        int4 d = edge4_at(ei, NE + t * 4, is64);
        atomicAdd(&g_deg[d.x], 1);
        atomicAdd(&g_deg[d.y], 1);
        atomicAdd(&g_deg[d.z], 1);
        atomicAdd(&g_deg[d.w], 1);
    }
}

// ---------------- launch 1: single-pass decoupled-lookback scan ----------------
__global__ void __launch_bounds__(1024) scan_k() {
    __shared__ int s[1024];
    __shared__ int blk_base;
    int b = blockIdx.x;
    int i = b * 1024 + threadIdx.x;
    int v = (i < NN) ? g_deg[i] : 0;
    s[threadIdx.x] = v;
    __syncthreads();
    for (int d = 1; d < 1024; d <<= 1) {
        int t = (threadIdx.x >= d) ? s[threadIdx.x - d] : 0;
        __syncthreads();
        s[threadIdx.x] += t;
        __syncthreads();
    }
    if (threadIdx.x == 1023) {
        int total = s[1023];
        g_blk_agg[b] = total;
        __threadfence();
        g_blk_flag[b] = 1;
        int base = 0;
        for (int p = b - 1; p >= 0; p--) {
            int f;
            while ((f = g_blk_flag[p]) == 0) {}
            if (f == 2) { base += g_blk_pfx[p]; break; }
            base += g_blk_agg[p];
        }
        g_blk_pfx[b] = base + total;
        __threadfence();
        g_blk_flag[b] = 2;
        blk_base = base;
    }
    __syncthreads();
    if (i < NN) {
        int o = blk_base + s[threadIdx.x] - v;
        g_off[i] = o;
        g_cursor[i] = o;
    }
    if (i == 0) g_off[NN] = NE;
}

// ---------------- launch 2: CSR fill, 4 edges/thread ----------------
__global__ void __launch_bounds__(256) csr_fill_k(const void* __restrict__ ei) {
    int is64 = detect_is64_block(ei);
    int t = blockIdx.x * 256 + threadIdx.x;
    if (t < NE / 4) {
        int4 s = edge4_at(ei, t * 4, is64);
        int4 d = edge4_at(ei, NE + t * 4, is64);
        g_csr[atomicAdd(&g_cursor[d.x], 1)] = s.x;
        g_csr[atomicAdd(&g_cursor[d.y], 1)] = s.y;
        g_csr[atomicAdd(&g_cursor[d.z], 1)] = s.z;
        g_csr[atomicAdd(&g_cursor[d.w], 1)] = s.w;
    }
}

// ---------------- launch 3 (PROFILED): fp16 mean aggregation ------------------
// Half-warp row scheme: each lane loads uint4 (16B); lanes 0-15 cover one
// edge's 256B row, lanes 16-31 the next edge's. 4x LDG.128 per 8 edges doubles
// bytes-in-flight vs LDG.64 and halves the loop trip count. Even/odd-edge
// partials merged by shfl.bfly(16) at the end.
__device__ __forceinline__ void acc_pair4(float4& a, float4& b, uint4 u, uint4 v) {
    __half2 s0 = __hadd2(*(__half2*)&u.x, *(__half2*)&v.x);
    __half2 s1 = __hadd2(*(__half2*)&u.y, *(__half2*)&v.y);
    __half2 s2 = __hadd2(*(__half2*)&u.z, *(__half2*)&v.z);
    __half2 s3 = __hadd2(*(__half2*)&u.w, *(__half2*)&v.w);
    float2 f0 = __half22float2(s0);
    float2 f1 = __half22float2(s1);
    float2 f2 = __half22float2(s2);
    float2 f3 = __half22float2(s3);
    a.x += f0.x; a.y += f0.y; a.z += f1.x; a.w += f1.y;
    b.x += f2.x; b.y += f2.y; b.z += f3.x; b.w += f3.y;
}

__device__ __forceinline__ void acc_one4(float4& a, float4& b, uint4 u) {
    float2 f0 = __half22float2(*(__half2*)&u.x);
    float2 f1 = __half22float2(*(__half2*)&u.y);
    float2 f2 = __half22float2(*(__half2*)&u.z);
    float2 f3 = __half22float2(*(__half2*)&u.w);
    a.x += f0.x; a.y += f0.y; a.z += f1.x; a.w += f1.y;
    b.x += f2.x; b.y += f2.y; b.z += f3.x; b.w += f3.y;
}

__global__ void __launch_bounds__(256) aggregate_k(const uint32_t* __restrict__ xin,
                                                   uint32_t* __restrict__ outp) {
    int warp = (blockIdx.x * blockDim.x + threadIdx.x) >> 5;
    int lane = threadIdx.x & 31;
    if (warp >= NN) return;
    int start = g_off[warp];
    int end   = g_off[warp + 1];
    const int hi  = lane >> 4;    // 0: even edges, 1: odd edges
    const int sub = lane & 15;    // 16B chunk within the 256B row
    const uint4* xv4 = (const uint4*)xin;   // row = 16 uint4

    float4 accA = make_float4(0.f, 0.f, 0.f, 0.f);  // dims 8*sub .. +4
    float4 accB = make_float4(0.f, 0.f, 0.f, 0.f);  // dims 8*sub+4 .. +8
    int k = start;

    // main: 8 edges / iter (4 per half-warp), 4x LDG.128 in flight
    for (; k + 8 <= end; k += 8) {
        int i0 = g_csr[k + 0 + hi];
        int i1 = g_csr[k + 2 + hi];
        int i2 = g_csr[k + 4 + hi];
        int i3 = g_csr[k + 6 + hi];
        uint4 v0 = xv4[(size_t)i0 * 16 + sub];
        uint4 v1 = xv4[(size_t)i1 * 16 + sub];
        uint4 v2 = xv4[(size_t)i2 * 16 + sub];
        uint4 v3 = xv4[(size_t)i3 * 16 + sub];
        acc_pair4(accA, accB, v0, v1);
        acc_pair4(accA, accB, v2, v3);
    }
    // 4-edge remainder (2 per half)
    if (k + 4 <= end) {
        int i0 = g_csr[k + 0 + hi];
        int i1 = g_csr[k + 2 + hi];
        uint4 v0 = xv4[(size_t)i0 * 16 + sub];
        uint4 v1 = xv4[(size_t)i1 * 16 + sub];
        acc_pair4(accA, accB, v0, v1);
        k += 4;
    }
    // 2-edge remainder (1 per half)
    if (k + 2 <= end) {
        int i0 = g_csr[k + hi];
        uint4 v0 = xv4[(size_t)i0 * 16 + sub];
        acc_one4(accA, accB, v0);
        k += 2;
    }
    // 1-edge tail (lo half only)
    if (k < end && hi == 0) {
        uint4 v0 = xv4[(size_t)g_csr[k] * 16 + sub];
        acc_one4(accA, accB, v0);
    }

    // merge even/odd-edge partials across half-warps
    float* pa = &accA.x;
    float* pb = &accB.x;
    #pragma unroll
    for (int i = 0; i < 4; i++) {
        pa[i] += __shfl_xor_sync(0xffffffffu, pa[i], 16);
        pb[i] += __shfl_xor_sync(0xffffffffu, pb[i], 16);
    }

    int deg = end - start;
    float inv = 1.0f / (float)(deg > 0 ? deg : 1);
    if (hi == 0) {
        uint4 o;
        o.x = pack_h2(accA.x * inv, accA.y * inv);
        o.y = pack_h2(accA.z * inv, accA.w * inv);
        o.z = pack_h2(accB.x * inv, accB.y * inv);
        o.w = pack_h2(accB.z * inv, accB.w * inv);
        ((uint4*)outp)[(size_t)warp * 16 + sub] = o;
    }
}

// ---------------- fp16 tensor-core fused dual GEMM (m16n8k16, fp32 accum) ----
#define ROWW 20                       // words per smem row (16 data + 4 pad)
#define BUFW (128 * ROWW)             // words per buffer

__device__ __forceinline__ void cp_async16(uint32_t smem, const void* gptr, int src_sz) {
    asm volatile("cp.async.ca.shared.global [%0], [%1], 16, %2;"
                 :: "r"(smem), "l"(gptr), "r"(src_sz));
}
__device__ __forceinline__ void cp_commit() {
    asm volatile("cp.async.commit_group;");
}
template <int N>
__device__ __forceinline__ void cp_wait() {
    asm volatile("cp.async.wait_group %0;" :: "n"(N));
}

template <bool RELU>   // RELU version emits fp16 output only
__global__ void __launch_bounds__(256) gemm_f16_k(
    const uint32_t* __restrict__ A1,   // mean16 [NN][64]
    const uint32_t* __restrict__ A2,   // x16/h16 [NN][64]
    const uint32_t* __restrict__ Wl,   // [C][64] fp16
    const uint32_t* __restrict__ Wr,   // [C][64] fp16
    const float*    __restrict__ bias, // [C]
    float*          __restrict__ outp, // [NN][C] fp32 (final layer)
    uint32_t*       __restrict__ out16)// [NN][64] fp16 (hidden layer)
{
    __shared__ uint32_t As[2][BUFW];
    __shared__ uint32_t Ws[2][BUFW];

    const int tid  = threadIdx.x;
    const int lane = tid & 31;
    const int wid  = tid >> 5;
    const int warpRow = wid >> 2;
    const int warpCol = wid & 3;
    const int nodeBase = blockIdx.x * 128;

    const int lr = lane >> 2;
    const int lc = lane & 3;

    const uint32_t as_base = (uint32_t)__cvta_generic_to_shared(&As[0][0]);
    const uint32_t ws_base = (uint32_t)__cvta_generic_to_shared(&Ws[0][0]);

    float acc[4][4][4] = {};

    auto stage = [&](int s, int buf) {
        const int half = s >> 2;
        const int kw   = (s & 3) * 16;
        const uint32_t* A = half ? A2 : A1;
        const uint32_t* W = half ? Wr : Wl;
        #pragma unroll
        for (int t = 0; t < 2; t++) {
            int idx = tid + t * 256;
            int row = idx >> 2;
            int q   = idx & 3;
            int gnode = nodeBase + row;
            uint32_t off = (buf * BUFW + row * ROWW + q * 4) * 4;
            cp_async16(as_base + off, &A[(size_t)gnode * 64 + kw + q * 4],
                       (gnode < NN) ? 16 : 0);
            cp_async16(ws_base + off, &W[row * 64 + kw + q * 4], 16);
        }
        cp_commit();
    };

    stage(0, 0);

    #pragma unroll 1
    for (int s = 0; s < 8; s++) {
        const int buf = s & 1;
        if (s < 7) stage(s + 1, buf ^ 1);
        if (s < 7) cp_wait<1>(); else cp_wait<0>();
        __syncthreads();

        const uint32_t* Ab = &As[buf][0];
        const uint32_t* Wb = &Ws[buf][0];

        #pragma unroll
        for (int ks = 0; ks < 2; ks++) {
            const int k0 = ks * 8;
            uint32_t bf[4][2];
            #pragma unroll
            for (int nt = 0; nt < 4; nt++) {
                int c = warpCol * 32 + nt * 8 + lr;
                bf[nt][0] = Wb[c * ROWW + k0 + lc];
                bf[nt][1] = Wb[c * ROWW + k0 + lc + 4];
            }
            #pragma unroll
            for (int mt = 0; mt < 4; mt++) {
                int r = warpRow * 64 + mt * 16 + lr;
                uint32_t a0 = Ab[r * ROWW + k0 + lc];
                uint32_t a1 = Ab[(r + 8) * ROWW + k0 + lc];
                uint32_t a2 = Ab[r * ROWW + k0 + lc + 4];
                uint32_t a3 = Ab[(r + 8) * ROWW + k0 + lc + 4];
                #pragma unroll
                for (int nt = 0; nt < 4; nt++) {
                    asm volatile(
                        "mma.sync.aligned.m16n8k16.row.col.f32.f16.f16.f32 "
                        "{%0,%1,%2,%3}, {%4,%5,%6,%7}, {%8,%9}, {%0,%1,%2,%3};"
                        : "+f"(acc[mt][nt][0]), "+f"(acc[mt][nt][1]),
                          "+f"(acc[mt][nt][2]), "+f"(acc[mt][nt][3])
                        : "r"(a0), "r"(a1), "r"(a2), "r"(a3),
                          "r"(bf[nt][0]), "r"(bf[nt][1]));
                }
            }
        }
        __syncthreads();
    }

    #pragma unroll
    for (int nt = 0; nt < 4; nt++) {
        int c = warpCol * 32 + nt * 8 + 2 * lc;
        float bb0 = bias[c];
        float bb1 = bias[c + 1];
        #pragma unroll
        for (int mt = 0; mt < 4; mt++) {
            int r0 = nodeBase + warpRow * 64 + mt * 16 + lr;
            int r1 = r0 + 8;
            float o0 = acc[mt][nt][0] + bb0;
            float o1 = acc[mt][nt][1] + bb1;
            float o2 = acc[mt][nt][2] + bb0;
            float o3 = acc[mt][nt][3] + bb1;
            if (RELU) {
                o0 = fmaxf(o0, 0.f); o1 = fmaxf(o1, 0.f);
                o2 = fmaxf(o2, 0.f); o3 = fmaxf(o3, 0.f);
                if (r0 < NN) out16[(size_t)r0 * 64 + (c >> 1)] = pack_h2(o0, o1);
                if (r1 < NN) out16[(size_t)r1 * 64 + (c >> 1)] = pack_h2(o2, o3);
            } else {
                if (r0 < NN) *(float2*)&outp[(size_t)r0 * C + c] = make_float2(o0, o1);
                if (r1 < NN) *(float2*)&outp[(size_t)r1 * C + c] = make_float2(o2, o3);
            }
        }
    }
}

// ---------------- trailing cleanup for next replay ----------------
__global__ void __launch_bounds__(256) cleanup_k() {
    int i = blockIdx.x * blockDim.x + threadIdx.x;
    if (i < NN) g_deg[i] = 0;
    if (i < NB) g_blk_flag[i] = 0;
}

// ---------------- launch ----------------
extern "C" void kernel_launch(void* const* d_in, const int* in_sizes, int n_in,
                              void* d_out, int out_size) {
    const float* x   = (const float*)d_in[0];
    const void*  ei  = d_in[1];
    const float* W1l = (const float*)d_in[2];
    const float* b1  = (const float*)d_in[3];
    const float* W1r = (const float*)d_in[4];
    const float* W2l = (const float*)d_in[5];
    const float* b2  = (const float*)d_in[6];
    const float* W2r = (const float*)d_in[7];
    float* out = (float*)d_out;

    uint32_t *x16, *mean16, *h16, *w1l, *w1r, *w2l, *w2r;
    cudaGetSymbolAddress((void**)&x16,    g_x16);
    cudaGetSymbolAddress((void**)&mean16, g_mean16);
    cudaGetSymbolAddress((void**)&h16,    g_h16);
    cudaGetSymbolAddress((void**)&w1l,    g_W1l_h);
    cudaGetSymbolAddress((void**)&w1r,    g_W1r_h);
    cudaGetSymbolAddress((void**)&w2l,    g_W2l_h);
    cudaGetSymbolAddress((void**)&w2r,    g_W2r_h);

    hist_cvt_k<<<CVT_BLOCKS + HIST_BLOCKS, 256>>>(ei, (const float4*)x,
                                                  W1l, W1r, W2l, W2r);           // 0
    scan_k<<<NB, 1024>>>();                                                      // 1
    csr_fill_k<<<(NE / 4 + 255) / 256, 256>>>(ei);                               // 2

    const int gemmGrid = (NN + 127) / 128;  // 782

    aggregate_k<<<(NN * 32 + 255) / 256, 256>>>(x16, mean16);                    // 3 <- profiled
    gemm_f16_k<true><<<gemmGrid, 256>>>(mean16, x16, w1l, w1r, b1, nullptr, h16); // 4
    aggregate_k<<<(NN * 32 + 255) / 256, 256>>>(h16, mean16);                    // 5
    gemm_f16_k<false><<<gemmGrid, 256>>>(mean16, h16, w2l, w2r, b2, out, nullptr); // 6
    cleanup_k<<<(NN + 255) / 256, 256>>>();                                      // 7
}